// round 3
// baseline (speedup 1.0000x reference)
#include <cuda_runtime.h>
#include <cuda_bf16.h>
#include <stdint.h>

#define NSPK 256
#define MUTT 64
#define DDIM 1024
#define NROWS (NSPK*MUTT)   // 16384

// ---------------- device scratch (no dynamic allocation allowed) ---------
__device__ __nv_bfloat16 g_emb_hi[(size_t)NROWS * DDIM];   // 32 MB
__device__ __nv_bfloat16 g_emb_lo[(size_t)NROWS * DDIM];   // 32 MB
__device__ __nv_bfloat16 g_c_hi[NSPK * DDIM];              // 512 KB
__device__ __nv_bfloat16 g_c_lo[NSPK * DDIM];              // 512 KB
__device__ float g_sum[NSPK * DDIM];                       // 1 MB
__device__ float g_q[NROWS];
__device__ float g_L[NSPK];
__device__ float g_L2[NSPK];

// ---------------- helpers -------------------------------------------------
static __device__ __forceinline__ uint32_t smem_u32(const void* p) {
    uint32_t a;
    asm("{ .reg .u64 t; cvta.to.shared.u64 t, %1; cvt.u32.u64 %0, t; }" : "=r"(a) : "l"(p));
    return a;
}
static __device__ __forceinline__ void cp16(uint32_t d, const void* s) {
    asm volatile("cp.async.cg.shared.global [%0], [%1], 16;\n" :: "r"(d), "l"(s));
}
static __device__ __forceinline__ void cp_commit() {
    asm volatile("cp.async.commit_group;\n" ::: "memory");
}
template <int N> static __device__ __forceinline__ void cp_wait() {
    asm volatile("cp.async.wait_group %0;\n" :: "n"(N) : "memory");
}
static __device__ __forceinline__ void ldsm4(uint32_t* r, uint32_t addr) {
    asm volatile("ldmatrix.sync.aligned.m8n8.x4.shared.b16 {%0,%1,%2,%3}, [%4];"
                 : "=r"(r[0]), "=r"(r[1]), "=r"(r[2]), "=r"(r[3]) : "r"(addr));
}
static __device__ __forceinline__ void mma16816(float* d, const uint32_t* a, const uint32_t* b) {
    asm volatile("mma.sync.aligned.m16n8k16.row.col.f32.bf16.bf16.f32 "
                 "{%0,%1,%2,%3}, {%4,%5,%6,%7}, {%8,%9}, {%0,%1,%2,%3};"
                 : "+f"(d[0]), "+f"(d[1]), "+f"(d[2]), "+f"(d[3])
                 : "r"(a[0]), "r"(a[1]), "r"(a[2]), "r"(a[3]), "r"(b[0]), "r"(b[1]));
}

// ======================= K1: stats + bf16 split ===========================
__global__ void __launch_bounds__(256) k1_stats_split(const float* __restrict__ in) {
    int spk = blockIdx.x, tid = threadIdx.x;
    int w = tid >> 5, l = tid & 31;
    __shared__ float qp[64][8];
    float a0 = 0.f, a1 = 0.f, a2 = 0.f, a3 = 0.f;
    const float4* src = (const float4*)(in + (size_t)spk * MUTT * DDIM);
    size_t rowbase = (size_t)spk * MUTT * DDIM;

    for (int r = 0; r < MUTT; r++) {
        float4 v = src[r * (DDIM / 4) + tid];
        a0 += v.x; a1 += v.y; a2 += v.z; a3 += v.w;
        float q = v.x * v.x + v.y * v.y + v.z * v.z + v.w * v.w;
        #pragma unroll
        for (int o = 16; o; o >>= 1) q += __shfl_down_sync(0xffffffffu, q, o);
        if (l == 0) qp[r][w] = q;

        __nv_bfloat16 hx = __float2bfloat16(v.x), hy = __float2bfloat16(v.y);
        __nv_bfloat16 hz = __float2bfloat16(v.z), hw_ = __float2bfloat16(v.w);
        __nv_bfloat16 lx = __float2bfloat16(v.x - __bfloat162float(hx));
        __nv_bfloat16 ly = __float2bfloat16(v.y - __bfloat162float(hy));
        __nv_bfloat16 lz = __float2bfloat16(v.z - __bfloat162float(hz));
        __nv_bfloat16 lw = __float2bfloat16(v.w - __bfloat162float(hw_));

        union { __nv_bfloat162 h2[2]; uint2 u; } ph, pl;
        ph.h2[0] = __halves2bfloat162(hx, hy); ph.h2[1] = __halves2bfloat162(hz, hw_);
        pl.h2[0] = __halves2bfloat162(lx, ly); pl.h2[1] = __halves2bfloat162(lz, lw);
        size_t eoff = rowbase + (size_t)r * DDIM + (size_t)tid * 4;
        *(uint2*)(g_emb_hi + eoff) = ph.u;
        *(uint2*)(g_emb_lo + eoff) = pl.u;
    }
    __syncthreads();
    if (tid < 64) {
        float s = 0.f;
        #pragma unroll
        for (int i = 0; i < 8; i++) s += qp[tid][i];
        g_q[spk * MUTT + tid] = s;
    }
    float4 s4; s4.x = a0; s4.y = a1; s4.z = a2; s4.w = a3;
    ((float4*)g_sum)[spk * (DDIM / 4) + tid] = s4;
}

// ======================= K2: centers ======================================
__global__ void __launch_bounds__(256) k2_center() {
    int spk = blockIdx.x, tid = threadIdx.x;
    int w = tid >> 5, l = tid & 31;
    __shared__ float wp[8];
    float4 s4 = ((const float4*)g_sum)[spk * (DDIM / 4) + tid];
    float4 m;
    m.x = s4.x * 0.015625f; m.y = s4.y * 0.015625f;
    m.z = s4.z * 0.015625f; m.w = s4.w * 0.015625f;
    float p = m.x * m.x + m.y * m.y + m.z * m.z + m.w * m.w;
    #pragma unroll
    for (int o = 16; o; o >>= 1) p += __shfl_down_sync(0xffffffffu, p, o);
    if (l == 0) wp[w] = p;
    __syncthreads();
    float ms = 0.f;
    #pragma unroll
    for (int i = 0; i < 8; i++) ms += wp[i];
    float r = 1.f / sqrtf(fmaxf(ms, 1e-12f));
    float cx = m.x * r, cy = m.y * r, cz = m.z * r, cw = m.w * r;

    __nv_bfloat16 hx = __float2bfloat16(cx), hy = __float2bfloat16(cy);
    __nv_bfloat16 hz = __float2bfloat16(cz), hw_ = __float2bfloat16(cw);
    __nv_bfloat16 lx = __float2bfloat16(cx - __bfloat162float(hx));
    __nv_bfloat16 ly = __float2bfloat16(cy - __bfloat162float(hy));
    __nv_bfloat16 lz = __float2bfloat16(cz - __bfloat162float(hz));
    __nv_bfloat16 lw = __float2bfloat16(cw - __bfloat162float(hw_));
    union { __nv_bfloat162 h2[2]; uint2 u; } ph, pl;
    ph.h2[0] = __halves2bfloat162(hx, hy); ph.h2[1] = __halves2bfloat162(hz, hw_);
    pl.h2[0] = __halves2bfloat162(lx, ly); pl.h2[1] = __halves2bfloat162(lz, lw);
    size_t off = (size_t)spk * DDIM + (size_t)tid * 4;
    *(uint2*)(g_c_hi + off) = ph.u;
    *(uint2*)(g_c_lo + off) = pl.u;

    if (tid == 0) {
        g_L[spk]  = 64.f * sqrtf(ms);
        g_L2[spk] = 4096.f * ms;
    }
}

// ======================= K3: HMMA GEMM + fused epilogue ===================
// CTA tile 128(M) x 256(N), BK=32 bf16. 8 warps: 2(M) x 4(N), warp 64x64.
// smem rows padded to 80B (40 bf16) -> ldmatrix conflict-free.
#define ROWB 80
#define A_HI 0
#define A_LO 10240
#define B_HI 20480
#define B_LO 40960
#define ST_STRIDE 61440
#define K3_SMEM (2 * ST_STRIDE)

static __device__ __forceinline__ void k3_loads(uint32_t sm, int s, int k, int tid, int ctaM) {
    uint32_t sb = sm + (uint32_t)s * ST_STRIDE;
    const char* ehi = (const char*)g_emb_hi;
    const char* elo = (const char*)g_emb_lo;
    const char* chi = (const char*)g_c_hi;
    const char* clo = (const char*)g_c_lo;
    size_t kbyte = (size_t)k * 64;   // k*32 bf16 * 2B
    // A: 512 chunks of 16B per array (128 rows x 4 chunks)
    {
        int c = tid;                             // i = 0
        int row = c >> 2; uint32_t sub = (c & 3) * 16u;
        size_t go = ((size_t)(ctaM * 128 + row)) * 2048 + kbyte + sub;
        cp16(sb + A_HI + (uint32_t)row * ROWB + sub, ehi + go);
        c = tid + 256; row = c >> 2; sub = (c & 3) * 16u;
        go = ((size_t)(ctaM * 128 + row)) * 2048 + kbyte + sub;
        cp16(sb + A_HI + (uint32_t)row * ROWB + sub, ehi + go);
        c = tid; row = c >> 2; sub = (c & 3) * 16u;
        go = ((size_t)(ctaM * 128 + row)) * 2048 + kbyte + sub;
        cp16(sb + A_LO + (uint32_t)row * ROWB + sub, elo + go);
        c = tid + 256; row = c >> 2; sub = (c & 3) * 16u;
        go = ((size_t)(ctaM * 128 + row)) * 2048 + kbyte + sub;
        cp16(sb + A_LO + (uint32_t)row * ROWB + sub, elo + go);
    }
    // B: 1024 chunks of 16B per array (256 rows x 4 chunks)
    #pragma unroll
    for (int i = 0; i < 4; i++) {
        int c = tid + i * 256;
        int row = c >> 2; uint32_t sub = (c & 3) * 16u;
        size_t go = (size_t)row * 2048 + kbyte + sub;
        cp16(sb + B_HI + (uint32_t)row * ROWB + sub, chi + go);
        cp16(sb + B_LO + (uint32_t)row * ROWB + sub, clo + go);
    }
}

__global__ void __launch_bounds__(256, 1) k3_gemm(const float* __restrict__ w_p,
                                                  const float* __restrict__ b_p,
                                                  float* __restrict__ out) {
    extern __shared__ char smem[];
    uint32_t sm = smem_u32(smem);
    int tid = threadIdx.x, wid = tid >> 5, lane = tid & 31, ctaM = blockIdx.x;
    int warpM = wid >> 2, warpN = wid & 3;

    // per-lane ldmatrix offsets (within stage, bytes)
    uint32_t aoff[4], boff[4];
    {
        uint32_t ars = (uint32_t)(lane & 15);
        uint32_t acs = (uint32_t)(lane >> 4) * 16u;
        uint32_t brs = (uint32_t)((lane & 7) + ((lane >> 4) << 3));
        uint32_t bcs = (uint32_t)((lane >> 3) & 1) * 16u;
        #pragma unroll
        for (int mt = 0; mt < 4; mt++)
            aoff[mt] = (uint32_t)(warpM * 64 + mt * 16 + ars) * ROWB + acs;
        #pragma unroll
        for (int np = 0; np < 4; np++)
            boff[np] = (uint32_t)(warpN * 64 + np * 16 + brs) * ROWB + bcs;
    }

    float acc[4][8][4];
    #pragma unroll
    for (int mt = 0; mt < 4; mt++)
        #pragma unroll
        for (int nt = 0; nt < 8; nt++)
            #pragma unroll
            for (int i = 0; i < 4; i++) acc[mt][nt][i] = 0.f;

    k3_loads(sm, 0, 0, tid, ctaM); cp_commit();
    k3_loads(sm, 1, 1, tid, ctaM); cp_commit();

    #pragma unroll 1
    for (int k = 0; k < 32; k++) {
        int s = k & 1;
        if (k < 31) cp_wait<1>(); else cp_wait<0>();
        __syncthreads();
        uint32_t sb = sm + (uint32_t)s * ST_STRIDE;

        #pragma unroll
        for (int ks = 0; ks < 2; ks++) {
            uint32_t kb = (uint32_t)ks * 32u;
            uint32_t ah[4][4], al[4][4], bh[8][2], bl[8][2];
            #pragma unroll
            for (int mt = 0; mt < 4; mt++) {
                ldsm4(ah[mt], sb + A_HI + aoff[mt] + kb);
                ldsm4(al[mt], sb + A_LO + aoff[mt] + kb);
            }
            #pragma unroll
            for (int np = 0; np < 4; np++) {
                uint32_t t[4];
                ldsm4(t, sb + B_HI + boff[np] + kb);
                bh[2 * np][0] = t[0]; bh[2 * np][1] = t[1];
                bh[2 * np + 1][0] = t[2]; bh[2 * np + 1][1] = t[3];
                ldsm4(t, sb + B_LO + boff[np] + kb);
                bl[2 * np][0] = t[0]; bl[2 * np][1] = t[1];
                bl[2 * np + 1][0] = t[2]; bl[2 * np + 1][1] = t[3];
            }
            #pragma unroll
            for (int mt = 0; mt < 4; mt++)
                #pragma unroll
                for (int nt = 0; nt < 8; nt++) {
                    mma16816(acc[mt][nt], ah[mt], bh[nt]);
                    mma16816(acc[mt][nt], ah[mt], bl[nt]);
                    mma16816(acc[mt][nt], al[mt], bh[nt]);
                }
        }

        if (k + 2 < 32) {
            __syncthreads();
            k3_loads(sm, s, k + 2, tid, ctaM);
            cp_commit();
        }
    }

    // ---- fused epilogue ----
    float W = w_p[0], Bb = b_p[0];
    #pragma unroll
    for (int mt = 0; mt < 4; mt++) {
        int r0 = ctaM * 128 + warpM * 64 + mt * 16 + (lane >> 2);
        int r1 = r0 + 8;
        int j0 = r0 >> 6, j1 = r1 >> 6;
        float q0 = g_q[r0], q1 = g_q[r1];
        float La = g_L[j0], L2a = g_L2[j0];
        float Lb = g_L[j1], L2b = g_L2[j1];
        #pragma unroll
        for (int nt = 0; nt < 8; nt++) {
            int c = warpN * 64 + nt * 8 + (lane & 3) * 2;
            float v0 = acc[mt][nt][0], v1 = acc[mt][nt][1];
            float v2 = acc[mt][nt][2], v3 = acc[mt][nt][3];
            if (c == j0 || c + 1 == j0) {
                float g = (c == j0) ? v0 : v1;
                float sv = g * La;
                float dg = (sv - q0) / sqrtf(fmaxf(L2a - 2.f * sv + q0, 1e-12f));
                if (c == j0) v0 = dg; else v1 = dg;
            }
            if (c == j1 || c + 1 == j1) {
                float g = (c == j1) ? v2 : v3;
                float sv = g * Lb;
                float dg = (sv - q1) / sqrtf(fmaxf(L2b - 2.f * sv + q1, 1e-12f));
                if (c == j1) v2 = dg; else v3 = dg;
            }
            float2 o0, o1;
            o0.x = W * v0 + Bb; o0.y = W * v1 + Bb;
            o1.x = W * v2 + Bb; o1.y = W * v3 + Bb;
            *(float2*)(out + (size_t)r0 * 256 + c) = o0;
            *(float2*)(out + (size_t)r1 * 256 + c) = o1;
        }
    }
}

// ======================= launch ===========================================
extern "C" void kernel_launch(void* const* d_in, const int* in_sizes, int n_in,
                              void* d_out, int out_size) {
    const float* in = (const float*)d_in[0];
    const float* w  = (const float*)d_in[1];
    const float* b  = (const float*)d_in[2];
    float* out = (float*)d_out;
    (void)in_sizes; (void)n_in; (void)out_size;

    cudaFuncSetAttribute(k3_gemm, cudaFuncAttributeMaxDynamicSharedMemorySize, K3_SMEM);

    k1_stats_split<<<NSPK, 256>>>(in);
    k2_center<<<NSPK, 256>>>();
    k3_gemm<<<NROWS / 128, 256, K3_SMEM>>>(w, b, out);
}